// round 13
// baseline (speedup 1.0000x reference)
#include <cuda_runtime.h>
#include <cstdint>

#define NUM_EXPERTS 64
#define TOP_K 4
#define EMA_DECAY 0.99f
#define NBINS (NUM_EXPERTS * NUM_EXPERTS)
#define NCTAS 444            // 3 CTAs/SM on 148 SMs
#define NTHREADS 512         // 1536 threads/SM, reg budget 42 -> MLP=4 fits

// Ordered-pair histogram scratch: P[a*64+b] over tokens, pairs (k1<k2).
// Symmetric coact = P + P^T.
// INVARIANT at kernel entry: g_P == 0, g_done == 0.
//  - first execution: static zero-init
//  - later executions: finalizing CTA re-zeroes g_P; atomicInc wraps g_done
__device__ unsigned int g_P[NBINS];
__device__ unsigned int g_done;

__device__ __forceinline__ uint32_t smem_addr_u32(const void* p) {
    uint32_t a;
    asm("{ .reg .u64 t; cvta.to.shared.u64 t, %1; cvt.u32.u64 %0, t; }"
        : "=r"(a) : "l"(p));
    return a;
}

// No-return shared reduction (no scoreboard wbar, fire-and-forget).
__device__ __forceinline__ void red_shared_inc(uint32_t byte_addr) {
    asm volatile("red.shared.add.u32 [%0], %1;" :: "r"(byte_addr), "r"(1u) : "memory");
}
// No-return global reduction (REDG).
__device__ __forceinline__ void red_global_add(unsigned int* p, unsigned int v) {
    asm volatile("red.global.add.u32 [%0], %1;" :: "l"(p), "r"(v) : "memory");
}

// Emit the 6 pair-REDs for one token. Byte offsets: ((x<<6)+y)<<2 = (x<<8)+(y<<2).
__device__ __forceinline__ void token_pairs(uint32_t sbase, int4 v) {
    uint32_t r0 = (uint32_t)v.x << 8, r1 = (uint32_t)v.y << 8, r2 = (uint32_t)v.z << 8;
    uint32_t c1 = (uint32_t)v.y << 2, c2 = (uint32_t)v.z << 2, c3 = (uint32_t)v.w << 2;
    red_shared_inc(sbase + r0 + c1);
    red_shared_inc(sbase + r0 + c2);
    red_shared_inc(sbase + r0 + c3);
    red_shared_inc(sbase + r1 + c2);
    red_shared_inc(sbase + r1 + c3);
    red_shared_inc(sbase + r2 + c3);
}

// ---------------------------------------------------------------------------
// Single fused kernel: histogram (red.shared) + last-CTA finalize.
// Indices are int32 [N,4] row-major -> one int4 (16B) load per token.
// Each thread processes 4 CONSECUTIVE tokens per iteration: 4 front-batched
// LDG.128 (MLP=4), 64B contiguous per thread, 2KB contiguous per warp.
// ---------------------------------------------------------------------------
__global__ void __launch_bounds__(NTHREADS, 3)
fused_tracker_kernel(const int4* __restrict__ idx,
                     const float* __restrict__ ema_in,
                     const float* __restrict__ coact_in,
                     float* __restrict__ out,
                     unsigned ntok) {
    __shared__ unsigned int sP[NBINS];
    __shared__ unsigned int sIsLast;

    for (int i = threadIdx.x; i < NBINS; i += NTHREADS) sP[i] = 0u;
    __syncthreads();

    const uint32_t sbase = smem_addr_u32(sP);

    const unsigned tid    = blockIdx.x * NTHREADS + threadIdx.x;
    const unsigned stride = gridDim.x * NTHREADS;

    // --- main loop: 4 tokens per iteration, front-batched loads ---
    const unsigned ngrp = ntok >> 2;           // groups of 4 tokens
    for (unsigned g = tid; g < ngrp; g += stride) {
        const int4* p = idx + 4u * g;
        int4 v0 = p[0];
        int4 v1 = p[1];
        int4 v2 = p[2];
        int4 v3 = p[3];
        token_pairs(sbase, v0);
        token_pairs(sbase, v1);
        token_pairs(sbase, v2);
        token_pairs(sbase, v3);
    }
    // tail tokens (ntok % 4)
    for (unsigned t = (ngrp << 2) + tid; t < ntok; t += stride)
        token_pairs(sbase, idx[t]);
    __syncthreads();   // BAR drains pending shared reductions (HW-native)

    // --- flush CTA-local histogram to global scratch (REDG, no return) ---
    for (int i = threadIdx.x; i < NBINS; i += NTHREADS) {
        unsigned v = sP[i];
        if (v) red_global_add(&g_P[i], v);
    }

    // --- last-CTA election (atomicInc self-wraps to 0 for next replay) ---
    __threadfence();   // order REDGs before the done-count
    __syncthreads();
    if (threadIdx.x == 0)
        sIsLast = (atomicInc(&g_done, gridDim.x - 1u) == gridDim.x - 1u) ? 1u : 0u;
    __syncthreads();
    if (!sIsLast) return;

    // --- finalize (last CTA only): stage g_P -> sP, zero g_P for next replay ---
    for (int i = threadIdx.x; i < NBINS; i += NTHREADS) {
        unsigned v = __ldcg(&g_P[i]);   // L2-coherent with the reductions
        sP[i] = v;
        g_P[i] = 0u;                    // restore invariant
    }
    __syncthreads();

    // coact output: coact_in + P + P^T   (integer-exact in fp32)
    for (int i = threadIdx.x; i < NBINS; i += NTHREADS) {
        int a = i >> 6;
        int b = i & 63;
        out[NUM_EXPERTS + i] =
            coact_in[i] + (float)(sP[(a << 6) + b] + sP[(b << 6) + a]);
    }

    // load EMA: 3*count[e] = rowsum(P)[e] + colsum(P)[e]  (K-1 = 3 pairs/occurrence)
    if (threadIdx.x < NUM_EXPERTS) {
        int e = threadIdx.x;
        unsigned s = 0u;
        #pragma unroll
        for (int j = 0; j < NUM_EXPERTS; j++) {
            s += sP[(e << 6) + j];
            s += sP[(j << 6) + e];
        }
        float count = (float)(s / 3u);          // exactly divisible by 3
        float load = count / (float)ntok;
        out[e] = ema_in[e] * EMA_DECAY + load * (1.0f - EMA_DECAY);
    }
}

// ---------------------------------------------------------------------------
// kernel_launch: ONE launch, graph-capturable, alloc-free.
// Inputs (metadata order):
//   d_in[0] expert_indices        int32  [N,4]
//   d_in[1] expert_weights        f32    [N,4]   (UNUSED by reference)
//   d_in[2] expert_load_ema       f32    [64]
//   d_in[3] expert_pair_coact     f32    [64,64]
// Output: f32 [64 + 4096] = (new_load_ema, new_coact) concatenated.
// ---------------------------------------------------------------------------
extern "C" void kernel_launch(void* const* d_in, const int* in_sizes, int n_in,
                              void* d_out, int out_size) {
    const int4* idx       = (const int4*)d_in[0];
    const float* ema_in   = (const float*)d_in[2];
    const float* coact_in = (const float*)d_in[3];
    float* out = (float*)d_out;

    unsigned ntok = (unsigned)(in_sizes[0] / TOP_K);

    fused_tracker_kernel<<<NCTAS, NTHREADS>>>(idx, ema_in, coact_in, out, ntok);
}

// round 14
// speedup vs baseline: 1.0982x; 1.0982x over previous
#include <cuda_runtime.h>
#include <cstdint>

#define NUM_EXPERTS 64
#define TOP_K 4
#define EMA_DECAY 0.99f
#define NBINS (NUM_EXPERTS * NUM_EXPERTS)
#define NCTAS 296             // 2 CTAs/SM on 148 SMs
#define NTHREADS 1024         // 64 warps/SM resident
#define CHUNK_TOK 2048        // tokens per staged chunk (32 KB)
#define CHUNK_BYTES (CHUNK_TOK * 16)

// dynamic SMEM layout
#define OFF_SP 0                          // 16 KB histogram
#define OFF_BUF0 (NBINS * 4)              // 32 KB staging buf 0
#define OFF_BUF1 (OFF_BUF0 + CHUNK_BYTES) // 32 KB staging buf 1
#define OFF_ISLAST (OFF_BUF1 + CHUNK_BYTES)
#define DSMEM_TOTAL (OFF_ISLAST + 64)

// Ordered-pair histogram scratch: P[a*64+b] over tokens, pairs (k1<k2).
// Symmetric coact = P + P^T.
// INVARIANT at kernel entry: g_P == 0, g_done == 0.
//  - first execution: static zero-init
//  - later executions: finalizing CTA re-zeroes g_P; atomicInc wraps g_done
__device__ unsigned int g_P[NBINS];
__device__ unsigned int g_done;

__device__ __forceinline__ uint32_t smem_addr_u32(const void* p) {
    uint32_t a;
    asm("{ .reg .u64 t; cvta.to.shared.u64 t, %1; cvt.u32.u64 %0, t; }"
        : "=r"(a) : "l"(p));
    return a;
}

// No-return shared reduction (no scoreboard wbar, fire-and-forget).
__device__ __forceinline__ void red_shared_inc(uint32_t byte_addr) {
    asm volatile("red.shared.add.u32 [%0], %1;" :: "r"(byte_addr), "r"(1u) : "memory");
}
// No-return global reduction (REDG).
__device__ __forceinline__ void red_global_add(unsigned int* p, unsigned int v) {
    asm volatile("red.global.add.u32 [%0], %1;" :: "l"(p), "r"(v) : "memory");
}
// 16-byte async copy global -> shared (bypass L1, no register dependency).
__device__ __forceinline__ void cp_async16(uint32_t smem_dst, const void* gsrc) {
    asm volatile("cp.async.cg.shared.global [%0], [%1], 16;"
                 :: "r"(smem_dst), "l"(gsrc) : "memory");
}
#define CP_COMMIT() asm volatile("cp.async.commit_group;" ::: "memory")
#define CP_WAIT_1() asm volatile("cp.async.wait_group 1;" ::: "memory")

// Emit the 6 pair-REDs for one token. Byte offsets: ((x<<6)+y)<<2 = (x<<8)+(y<<2).
__device__ __forceinline__ void token_pairs(uint32_t sbase, int4 v) {
    uint32_t r0 = (uint32_t)v.x << 8, r1 = (uint32_t)v.y << 8, r2 = (uint32_t)v.z << 8;
    uint32_t c1 = (uint32_t)v.y << 2, c2 = (uint32_t)v.z << 2, c3 = (uint32_t)v.w << 2;
    red_shared_inc(sbase + r0 + c1);
    red_shared_inc(sbase + r0 + c2);
    red_shared_inc(sbase + r0 + c3);
    red_shared_inc(sbase + r1 + c2);
    red_shared_inc(sbase + r1 + c3);
    red_shared_inc(sbase + r2 + c3);
}

// Stage one 2048-token chunk into a shared buffer (2 x 16B cp.async per thread).
__device__ __forceinline__ void stage_chunk(uint32_t bufaddr, const int4* idx,
                                            unsigned chunk, unsigned ntok,
                                            unsigned tid) {
    unsigned base = chunk * CHUNK_TOK;
    unsigned t0 = base + tid;
    unsigned t1 = base + 1024u + tid;
    // clamp OOB sources to a valid token (skipped at process time)
    if (t0 >= ntok) t0 = ntok - 1u;
    if (t1 >= ntok) t1 = ntok - 1u;
    cp_async16(bufaddr + tid * 16u, idx + t0);
    cp_async16(bufaddr + 16384u + tid * 16u, idx + t1);
}

// ---------------------------------------------------------------------------
// Single fused kernel: cp.async-staged histogram + last-CTA finalize.
// Indices are int32 [N,4] row-major. LDG latency is off the dependency
// chain: chunks prefetched into SMEM while previous chunk's REDs run.
// ---------------------------------------------------------------------------
__global__ void __launch_bounds__(NTHREADS, 2)
fused_tracker_kernel(const int4* __restrict__ idx,
                     const float* __restrict__ ema_in,
                     const float* __restrict__ coact_in,
                     float* __restrict__ out,
                     unsigned ntok) {
    extern __shared__ char dsm[];
    unsigned int* sP = (unsigned int*)(dsm + OFF_SP);
    const unsigned tid = threadIdx.x;

    for (int i = tid; i < NBINS; i += NTHREADS) sP[i] = 0u;
    // no syncthreads needed yet: first REDs happen after the first wait+sync below

    const uint32_t sbase   = smem_addr_u32(sP);
    const uint32_t bufaddr = smem_addr_u32(dsm + OFF_BUF0);

    const unsigned nchunks = (ntok + CHUNK_TOK - 1u) / CHUNK_TOK;

    // prologue: stage this CTA's first chunk
    unsigned c = blockIdx.x;
    if (c < nchunks) stage_chunk(bufaddr, idx, c, ntok, tid);
    CP_COMMIT();
    __syncthreads();   // also covers sP zero-init visibility

    unsigned sel = 0;
    while (c < nchunks) {
        // stage next chunk into the other buffer (empty commit keeps counts aligned)
        unsigned nextc = c + gridDim.x;
        if (nextc < nchunks)
            stage_chunk(bufaddr + (sel ^ 1u) * CHUNK_BYTES, idx, nextc, ntok, tid);
        CP_COMMIT();

        CP_WAIT_1();          // chunk c's group complete (next may be in flight)
        __syncthreads();      // make staged data CTA-visible

        // process 2 tokens/thread from SMEM (LDS.128 x2, 29-cyc latency)
        const int4* buf = (const int4*)(dsm + OFF_BUF0 + sel * CHUNK_BYTES);
        unsigned base = c * CHUNK_TOK;
        if (base + CHUNK_TOK <= ntok) {          // fast path: full chunk
            int4 v0 = buf[2u * tid];
            int4 v1 = buf[2u * tid + 1u];
            token_pairs(sbase, v0);
            token_pairs(sbase, v1);
        } else {                                 // tail chunk
            unsigned t0 = base + 2u * tid;
            if (t0 < ntok) token_pairs(sbase, buf[2u * tid]);
            if (t0 + 1u < ntok) token_pairs(sbase, buf[2u * tid + 1u]);
        }
        __syncthreads();      // buffer reusable for chunk c + 2*gridDim

        c = nextc;
        sel ^= 1u;
    }
    __syncthreads();   // drain pending shared reductions (BAR is HW-native drain)

    // --- flush CTA-local histogram to global scratch (REDG, no return) ---
    for (int i = tid; i < NBINS; i += NTHREADS) {
        unsigned v = sP[i];
        if (v) red_global_add(&g_P[i], v);
    }

    // --- last-CTA election (atomicInc self-wraps to 0 for next replay) ---
    __threadfence();   // order REDGs before the done-count
    __syncthreads();
    unsigned* isLast = (unsigned*)(dsm + OFF_ISLAST);
    if (tid == 0)
        *isLast = (atomicInc(&g_done, gridDim.x - 1u) == gridDim.x - 1u) ? 1u : 0u;
    __syncthreads();
    if (!*isLast) return;

    // --- finalize (last CTA only): stage g_P -> sP, zero g_P for next replay ---
    for (int i = tid; i < NBINS; i += NTHREADS) {
        unsigned v = __ldcg(&g_P[i]);   // L2-coherent with the reductions
        sP[i] = v;
        g_P[i] = 0u;                    // restore invariant
    }
    __syncthreads();

    // coact output: coact_in + P + P^T   (integer-exact in fp32)
    for (int i = tid; i < NBINS; i += NTHREADS) {
        int a = i >> 6;
        int b = i & 63;
        out[NUM_EXPERTS + i] =
            coact_in[i] + (float)(sP[(a << 6) + b] + sP[(b << 6) + a]);
    }

    // load EMA: 3*count[e] = rowsum(P)[e] + colsum(P)[e]  (K-1 = 3 pairs/occurrence)
    if (tid < NUM_EXPERTS) {
        int e = tid;
        unsigned s = 0u;
        #pragma unroll
        for (int j = 0; j < NUM_EXPERTS; j++) {
            s += sP[(e << 6) + j];
            s += sP[(j << 6) + e];
        }
        float count = (float)(s / 3u);          // exactly divisible by 3
        float load = count / (float)ntok;
        out[e] = ema_in[e] * EMA_DECAY + load * (1.0f - EMA_DECAY);
    }
}

// ---------------------------------------------------------------------------
// kernel_launch: ONE launch, graph-capturable, alloc-free.
// Inputs (metadata order):
//   d_in[0] expert_indices        int32  [N,4]
//   d_in[1] expert_weights        f32    [N,4]   (UNUSED by reference)
//   d_in[2] expert_load_ema       f32    [64]
//   d_in[3] expert_pair_coact     f32    [64,64]
// Output: f32 [64 + 4096] = (new_load_ema, new_coact) concatenated.
// ---------------------------------------------------------------------------
extern "C" void kernel_launch(void* const* d_in, const int* in_sizes, int n_in,
                              void* d_out, int out_size) {
    const int4* idx       = (const int4*)d_in[0];
    const float* ema_in   = (const float*)d_in[2];
    const float* coact_in = (const float*)d_in[3];
    float* out = (float*)d_out;

    unsigned ntok = (unsigned)(in_sizes[0] / TOP_K);

    cudaFuncSetAttribute(fused_tracker_kernel,
                         cudaFuncAttributeMaxDynamicSharedMemorySize, DSMEM_TOTAL);

    fused_tracker_kernel<<<NCTAS, NTHREADS, DSMEM_TOTAL>>>(idx, ema_in, coact_in, out, ntok);
}

// round 15
// speedup vs baseline: 1.1116x; 1.0122x over previous
#include <cuda_runtime.h>
#include <cstdint>

#define NUM_EXPERTS 64
#define TOP_K 4
#define EMA_DECAY 0.99f
#define NBINS (NUM_EXPERTS * NUM_EXPERTS)
#define NCTAS 296             // 2 CTAs/SM on 148 SMs
#define NTHREADS 1024         // 64 warps/SM resident
#define DEPTH 4               // per-thread cp.async pipeline depth

// dynamic SMEM layout: histogram + slot-major ring (DEPTH slabs of 16KB)
#define OFF_SP 0
#define OFF_RING (NBINS * 4)                       // 16 KB
#define SLOT_BYTES (NTHREADS * 16)                 // 16 KB per slot slab
#define OFF_ISLAST (OFF_RING + DEPTH * SLOT_BYTES) // 16 + 64 KB
#define DSMEM_TOTAL (OFF_ISLAST + 64)

// Ordered-pair histogram scratch: P[a*64+b] over tokens, pairs (k1<k2).
// Symmetric coact = P + P^T.
// INVARIANT at kernel entry: g_P == 0, g_done == 0.
//  - first execution: static zero-init
//  - later executions: finalizing CTA re-zeroes g_P; atomicInc wraps g_done
__device__ unsigned int g_P[NBINS];
__device__ unsigned int g_done;

__device__ __forceinline__ uint32_t smem_addr_u32(const void* p) {
    uint32_t a;
    asm("{ .reg .u64 t; cvta.to.shared.u64 t, %1; cvt.u32.u64 %0, t; }"
        : "=r"(a) : "l"(p));
    return a;
}
// No-return shared reduction (no scoreboard wbar, fire-and-forget).
__device__ __forceinline__ void red_shared_inc(uint32_t byte_addr) {
    asm volatile("red.shared.add.u32 [%0], %1;" :: "r"(byte_addr), "r"(1u) : "memory");
}
// No-return global reduction (REDG).
__device__ __forceinline__ void red_global_add(unsigned int* p, unsigned int v) {
    asm volatile("red.global.add.u32 [%0], %1;" :: "l"(p), "r"(v) : "memory");
}
// 16-byte async copy global -> shared.
__device__ __forceinline__ void cp_async16(uint32_t smem_dst, const void* gsrc) {
    asm volatile("cp.async.cg.shared.global [%0], [%1], 16;"
                 :: "r"(smem_dst), "l"(gsrc) : "memory");
}
#define CP_COMMIT()  asm volatile("cp.async.commit_group;" ::: "memory")
#define CP_WAIT_3()  asm volatile("cp.async.wait_group 3;" ::: "memory")
#define CP_WAIT_0()  asm volatile("cp.async.wait_group 0;" ::: "memory")
// 16B shared load.
__device__ __forceinline__ int4 lds128(uint32_t addr) {
    int4 v;
    asm volatile("ld.shared.v4.b32 {%0,%1,%2,%3}, [%4];"
                 : "=r"(v.x), "=r"(v.y), "=r"(v.z), "=r"(v.w) : "r"(addr));
    return v;
}

// Emit the 6 pair-REDs for one token. Byte offsets: ((x<<6)+y)<<2 = (x<<8)+(y<<2).
__device__ __forceinline__ void token_pairs(uint32_t sbase, int4 v) {
    uint32_t r0 = (uint32_t)v.x << 8, r1 = (uint32_t)v.y << 8, r2 = (uint32_t)v.z << 8;
    uint32_t c1 = (uint32_t)v.y << 2, c2 = (uint32_t)v.z << 2, c3 = (uint32_t)v.w << 2;
    red_shared_inc(sbase + r0 + c1);
    red_shared_inc(sbase + r0 + c2);
    red_shared_inc(sbase + r0 + c3);
    red_shared_inc(sbase + r1 + c2);
    red_shared_inc(sbase + r1 + c3);
    red_shared_inc(sbase + r2 + c3);
}

// ---------------------------------------------------------------------------
// Single fused kernel: per-THREAD cp.async ring (no barriers in mainloop).
// Each thread pipelines DEPTH tokens through its private 16B SMEM slots:
//   wait_group 3 -> LDS.128 -> 6 REDs -> cp.async refill -> commit.
// LDG latency fully overlapped; warp never stalls on DRAM in steady state.
// ---------------------------------------------------------------------------
__global__ void __launch_bounds__(NTHREADS, 2)
fused_tracker_kernel(const int4* __restrict__ idx,
                     const float* __restrict__ ema_in,
                     const float* __restrict__ coact_in,
                     float* __restrict__ out,
                     unsigned ntok) {
    extern __shared__ char dsm[];
    unsigned int* sP = (unsigned int*)(dsm + OFF_SP);
    const unsigned tid = threadIdx.x;

    for (int i = tid; i < NBINS; i += NTHREADS) sP[i] = 0u;

    const uint32_t sbase = smem_addr_u32(sP);
    const uint32_t ring  = smem_addr_u32(dsm + OFF_RING) + tid * 16u;

    const unsigned g0     = blockIdx.x * NTHREADS + tid;
    const unsigned stride = gridDim.x * NTHREADS;
    const unsigned nIter  = (ntok - g0 + stride - 1u) / stride;   // per-thread count
    const unsigned last   = ntok - 1u;

    // prologue: fill DEPTH slots (clamped source; invalid tokens skipped later)
    #pragma unroll
    for (unsigned s = 0; s < DEPTH; s++) {
        unsigned t = g0 + s * stride;
        cp_async16(ring + s * SLOT_BYTES, idx + (t > last ? last : t));
        CP_COMMIT();
    }
    __syncthreads();   // sP zero-init visible before first RED

    // main loop: one token per iteration, no CTA barriers
    for (unsigned i = 0; i < nIter; i++) {
        CP_WAIT_3();                       // slot (i % DEPTH) group complete
        int4 v = lds128(ring + (i & (DEPTH - 1u)) * SLOT_BYTES);
        // refill this slot with token i+DEPTH (empty commit keeps accounting)
        unsigned tn = g0 + (i + DEPTH) * stride;
        if (tn <= last) cp_async16(ring + (i & (DEPTH - 1u)) * SLOT_BYTES, idx + tn);
        CP_COMMIT();
        token_pairs(sbase, v);
    }
    CP_WAIT_0();       // retire outstanding groups before smem reuse
    __syncthreads();   // drain pending shared reductions (BAR is HW-native drain)

    // --- flush CTA-local histogram to global scratch (REDG, no return) ---
    for (int i = tid; i < NBINS; i += NTHREADS) {
        unsigned v = sP[i];
        if (v) red_global_add(&g_P[i], v);
    }

    // --- last-CTA election (atomicInc self-wraps to 0 for next replay) ---
    __threadfence();   // order REDGs before the done-count
    __syncthreads();
    unsigned* isLast = (unsigned*)(dsm + OFF_ISLAST);
    if (tid == 0)
        *isLast = (atomicInc(&g_done, gridDim.x - 1u) == gridDim.x - 1u) ? 1u : 0u;
    __syncthreads();
    if (!*isLast) return;

    // --- finalize (last CTA only): stage g_P -> sP, zero g_P for next replay ---
    for (int i = tid; i < NBINS; i += NTHREADS) {
        unsigned v = __ldcg(&g_P[i]);   // L2-coherent with the reductions
        sP[i] = v;
        g_P[i] = 0u;                    // restore invariant
    }
    __syncthreads();

    // coact output: coact_in + P + P^T   (integer-exact in fp32)
    for (int i = tid; i < NBINS; i += NTHREADS) {
        int a = i >> 6;
        int b = i & 63;
        out[NUM_EXPERTS + i] =
            coact_in[i] + (float)(sP[(a << 6) + b] + sP[(b << 6) + a]);
    }

    // load EMA: 3*count[e] = rowsum(P)[e] + colsum(P)[e]  (K-1 = 3 pairs/occurrence)
    if (tid < NUM_EXPERTS) {
        int e = tid;
        unsigned s = 0u;
        #pragma unroll
        for (int j = 0; j < NUM_EXPERTS; j++) {
            s += sP[(e << 6) + j];
            s += sP[(j << 6) + e];
        }
        float count = (float)(s / 3u);          // exactly divisible by 3
        float load = count / (float)ntok;
        out[e] = ema_in[e] * EMA_DECAY + load * (1.0f - EMA_DECAY);
    }
}

// ---------------------------------------------------------------------------
// kernel_launch: ONE launch, graph-capturable, alloc-free.
// Inputs (metadata order):
//   d_in[0] expert_indices        int32  [N,4]
//   d_in[1] expert_weights        f32    [N,4]   (UNUSED by reference)
//   d_in[2] expert_load_ema       f32    [64]
//   d_in[3] expert_pair_coact     f32    [64,64]
// Output: f32 [64 + 4096] = (new_load_ema, new_coact) concatenated.
// ---------------------------------------------------------------------------
extern "C" void kernel_launch(void* const* d_in, const int* in_sizes, int n_in,
                              void* d_out, int out_size) {
    const int4* idx       = (const int4*)d_in[0];
    const float* ema_in   = (const float*)d_in[2];
    const float* coact_in = (const float*)d_in[3];
    float* out = (float*)d_out;

    unsigned ntok = (unsigned)(in_sizes[0] / TOP_K);

    cudaFuncSetAttribute(fused_tracker_kernel,
                         cudaFuncAttributeMaxDynamicSharedMemorySize, DSMEM_TOTAL);

    fused_tracker_kernel<<<NCTAS, NTHREADS, DSMEM_TOTAL>>>(idx, ema_in, coact_in, out, ntok);
}